// round 3
// baseline (speedup 1.0000x reference)
#include <cuda_runtime.h>
#include <math.h>

// Problem constants (fixed by setup_inputs)
#define NN   50000
#define EE   800000
#define FF   128
#define HH   64
#define CC   16
#define KG   8          // gaussian kernels

// ---------------- scratch (static device globals; no allocation) -------------
__device__ int   g_rows[EE];
__device__ int   g_cols[EE];
__device__ int   g_cnt[NN];
__device__ int   g_idx64;
__device__ float g_gx1[(size_t)NN * KG * HH];   // x @ g1_w   [N][K*H]
__device__ float g_agg1[NN * HH];
__device__ float g_h[NN * HH];
__device__ float g_gx2[(size_t)NN * KG * CC];   // h @ g2_w   [N][K*C]
__device__ float g_agg2[NN * CC];

// ---------------- dtype detect ------------------------------------------------
__global__ void detect_kernel(const int* __restrict__ ei_words) {
    // int64 little-endian with values < 2^31 -> every odd 32-bit word of the
    // first 128 entries is zero. int32 node ids in [0,50000) -> impossible.
    int allz = 1;
    for (int i = 0; i < 128; i++) {
        if (ei_words[2 * i + 1] != 0) { allz = 0; break; }
    }
    g_idx64 = allz;
}

// ---------------- zero accumulators ------------------------------------------
__global__ void zero_kernel(int N) {
    int i = blockIdx.x * blockDim.x + threadIdx.x;
    if (i < N * HH) g_agg1[i] = 0.f;
    if (i < N * CC) g_agg2[i] = 0.f;
    if (i < N)      g_cnt[i]  = 0;
}

// ---------------- edge index normalization + degree count --------------------
__global__ void convert_edges(const void* __restrict__ ei, int E) {
    int e = blockIdx.x * blockDim.x + threadIdx.x;
    if (e >= E) return;
    int r, c;
    if (g_idx64) {
        const long long* p = (const long long*)ei;
        r = (int)p[e];
        c = (int)p[(size_t)E + e];
    } else {
        const int* p = (const int*)ei;
        r = p[e];
        c = p[E + e];
    }
    g_rows[e] = r;
    g_cols[e] = c;
    atomicAdd(&g_cnt[c], 1);
}

// ---------------- naive GEMM 1: gx1[n][c] = sum_f x[n][f] * g1_w[f][c] -------
// One thread per output element. c in [0, K*H=512).
__global__ void gx1_kernel(const float* __restrict__ x, const float* __restrict__ g1w,
                           int N) {
    int idx = blockIdx.x * blockDim.x + threadIdx.x;
    if (idx >= N * KG * HH) return;
    int n = idx / (KG * HH);
    int c = idx % (KG * HH);
    float s = 0.f;
    for (int f = 0; f < FF; f++)
        s += x[(size_t)n * FF + f] * g1w[(size_t)f * (KG * HH) + c];
    g_gx1[idx] = s;
}

// ---------------- edge stage 1: one THREAD per edge ---------------------------
// Literal transcription: gauss[k] = exp(-0.5 * sum_d (p_d - mu[k,d])^2/(eps+sig[k,d]^2))
// msg[o] = sum_k gauss[k] * gx1[row][k*H + o]; scatter-add to agg1[col].
__global__ void edge1_kernel(const float* __restrict__ ea,
                             const float* __restrict__ mu1,
                             const float* __restrict__ sig1, int E) {
    int e = blockIdx.x * blockDim.x + threadIdx.x;
    if (e >= E) return;
    int r = g_rows[e], c = g_cols[e];
    float p0 = ea[2 * (size_t)e];
    float p1 = ea[2 * (size_t)e + 1];
    float gk[KG];
#pragma unroll
    for (int k = 0; k < KG; k++) {
        float mx = mu1[k * 2], my = mu1[k * 2 + 1];
        float sx = sig1[k * 2], sy = sig1[k * 2 + 1];
        float dx = p0 - mx, dy = p1 - my;
        gk[k] = expf(-0.5f * (dx * dx / (1e-15f + sx * sx) +
                              dy * dy / (1e-15f + sy * sy)));
    }
    const float* gx = g_gx1 + (size_t)r * (KG * HH);
    float* dst = g_agg1 + (size_t)c * HH;
    for (int o = 0; o < HH; o++) {
        float s = 0.f;
#pragma unroll
        for (int k = 0; k < KG; k++)
            s += gk[k] * gx[k * HH + o];
        atomicAdd(dst + o, s);
    }
}

// ---------------- node stage 1: mean + naive root matvec + bias + elu --------
__global__ void node1_kernel(const float* __restrict__ x,
                             const float* __restrict__ root1,
                             const float* __restrict__ bias1, int N) {
    int idx = blockIdx.x * blockDim.x + threadIdx.x;
    if (idx >= N * HH) return;
    int n = idx / HH, o = idx % HH;
    float cnt = fmaxf((float)g_cnt[n], 1.0f);
    float root = 0.f;
    for (int f = 0; f < FF; f++)
        root += x[(size_t)n * FF + f] * root1[(size_t)f * HH + o];
    float v = g_agg1[idx] / cnt + root + bias1[o];
    g_h[idx] = v > 0.f ? v : expm1f(v);
}

// ---------------- naive GEMM 2: gx2[n][c] = sum_f h[n][f] * g2_w[f][c] -------
__global__ void gx2_kernel(const float* __restrict__ g2w, int N) {
    int idx = blockIdx.x * blockDim.x + threadIdx.x;
    if (idx >= N * KG * CC) return;
    int n = idx / (KG * CC);
    int c = idx % (KG * CC);
    float s = 0.f;
    for (int f = 0; f < HH; f++)
        s += g_h[(size_t)n * HH + f] * g2w[(size_t)f * (KG * CC) + c];
    g_gx2[idx] = s;
}

// ---------------- edge stage 2: one THREAD per edge ---------------------------
__global__ void edge2_kernel(const float* __restrict__ ea,
                             const float* __restrict__ mu2,
                             const float* __restrict__ sig2, int E) {
    int e = blockIdx.x * blockDim.x + threadIdx.x;
    if (e >= E) return;
    int r = g_rows[e], c = g_cols[e];
    float p0 = ea[2 * (size_t)e];
    float p1 = ea[2 * (size_t)e + 1];
    float gk[KG];
#pragma unroll
    for (int k = 0; k < KG; k++) {
        float mx = mu2[k * 2], my = mu2[k * 2 + 1];
        float sx = sig2[k * 2], sy = sig2[k * 2 + 1];
        float dx = p0 - mx, dy = p1 - my;
        gk[k] = expf(-0.5f * (dx * dx / (1e-15f + sx * sx) +
                              dy * dy / (1e-15f + sy * sy)));
    }
    const float* gx = g_gx2 + (size_t)r * (KG * CC);
    float* dst = g_agg2 + (size_t)c * CC;
    for (int o = 0; o < CC; o++) {
        float s = 0.f;
#pragma unroll
        for (int k = 0; k < KG; k++)
            s += gk[k] * gx[k * CC + o];
        atomicAdd(dst + o, s);
    }
}

// ---------------- node stage 2: mean + naive root + bias + log_softmax -------
__global__ void node2_kernel(const float* __restrict__ root2,
                             const float* __restrict__ bias2,
                             float* __restrict__ out, int N) {
    int n = blockIdx.x * blockDim.x + threadIdx.x;
    if (n >= N) return;
    float cnt = fmaxf((float)g_cnt[n], 1.0f);
    float vals[CC];
    float m = -1e30f;
    for (int c = 0; c < CC; c++) {
        float root = 0.f;
        for (int f = 0; f < HH; f++)
            root += g_h[(size_t)n * HH + f] * root2[(size_t)f * CC + c];
        float v = g_agg2[(size_t)n * CC + c] / cnt + root + bias2[c];
        vals[c] = v;
        m = fmaxf(m, v);
    }
    float s = 0.f;
    for (int c = 0; c < CC; c++) s += expf(vals[c] - m);
    float lse = m + logf(s);
    for (int c = 0; c < CC; c++) out[(size_t)n * CC + c] = vals[c] - lse;
}

// ---------------- launch -----------------------------------------------------
extern "C" void kernel_launch(void* const* d_in, const int* in_sizes, int n_in,
                              void* d_out, int out_size) {
    const float* x      = (const float*)d_in[0];
    const void*  ei     = d_in[1];
    const float* ea     = (const float*)d_in[2];
    const float* g1_w   = (const float*)d_in[3];
    const float* mu1    = (const float*)d_in[4];
    const float* sig1   = (const float*)d_in[5];
    const float* root1  = (const float*)d_in[6];
    const float* bias1  = (const float*)d_in[7];
    const float* g2_w   = (const float*)d_in[8];
    const float* mu2    = (const float*)d_in[9];
    const float* sig2   = (const float*)d_in[10];
    const float* root2  = (const float*)d_in[11];
    const float* bias2  = (const float*)d_in[12];
    float* out = (float*)d_out;

    int N = in_sizes[0] / FF;       // 50000
    int E = in_sizes[2] / 2;        // 800000 (edge_attr is [E,2])

    detect_kernel<<<1, 1>>>((const int*)ei);
    zero_kernel<<<(N * HH + 255) / 256, 256>>>(N);
    convert_edges<<<(E + 255) / 256, 256>>>(ei, E);

    // layer 1
    gx1_kernel<<<(N * KG * HH + 255) / 256, 256>>>(x, g1_w, N);
    edge1_kernel<<<(E + 255) / 256, 256>>>(ea, mu1, sig1, E);
    node1_kernel<<<(N * HH + 255) / 256, 256>>>(x, root1, bias1, N);

    // layer 2
    gx2_kernel<<<(N * KG * CC + 255) / 256, 256>>>(g2_w, N);
    edge2_kernel<<<(E + 255) / 256, 256>>>(ea, mu2, sig2, E);
    node2_kernel<<<(N + 255) / 256, 256>>>(root2, bias2, out, N);
}

// round 7
// speedup vs baseline: 2.2369x; 2.2369x over previous
#include <cuda_runtime.h>
#include <math.h>

// Problem constants (fixed by setup_inputs)
#define NN   50000
#define EE   800000
#define FF   128
#define HH   64
#define CC   16
#define KG   8          // gaussian kernels

// ---------------- scratch (static device globals; no allocation) -------------
__device__ int   g_rows[EE];
__device__ int   g_cols[EE];
__device__ int   g_cnt[NN];
__device__ int   g_idx64;
__device__ float g_gx1[(size_t)NN * KG * HH];   // x @ g1_w   [N][512]
__device__ float g_agg1[NN * HH];
__device__ float g_h[NN * HH];
__device__ float g_gx2[(size_t)NN * KG * CC];   // h @ g2_w   [N][128]
__device__ float g_agg2[NN * CC];

// ---------------- dtype detect ------------------------------------------------
__global__ void detect_kernel(const int* __restrict__ ei_words) {
    // int64 little-endian with values < 2^31 -> every odd 32-bit word of the
    // first 128 entries is zero. int32 node ids in [0,50000) -> impossible.
    int allz = 1;
    for (int i = 0; i < 128; i++) {
        if (ei_words[2 * i + 1] != 0) { allz = 0; break; }
    }
    g_idx64 = allz;
}

// ---------------- zero accumulators ------------------------------------------
__global__ void zero_kernel(int N) {
    int i = blockIdx.x * blockDim.x + threadIdx.x;
    if (i < N * HH) g_agg1[i] = 0.f;
    if (i < N * CC) g_agg2[i] = 0.f;
    if (i < N)      g_cnt[i]  = 0;
}

// ---------------- edge index normalization + degree count --------------------
__global__ void convert_edges(const void* __restrict__ ei, int E) {
    int e = blockIdx.x * blockDim.x + threadIdx.x;
    if (e >= E) return;
    int r, c;
    if (g_idx64) {
        const long long* p = (const long long*)ei;
        r = (int)p[e];
        c = (int)p[(size_t)E + e];
    } else {
        const int* p = (const int*)ei;
        r = p[e];
        c = p[E + e];
    }
    g_rows[e] = r;
    g_cols[e] = c;
    atomicAdd(&g_cnt[c], 1);
}

// ---------------- naive GEMM 1: gx1[n][c] = sum_f x[n][f] * g1_w[f][c] -------
// One thread per output element (PROVEN in R3 -- do not touch).
__global__ void gx1_kernel(const float* __restrict__ x, const float* __restrict__ g1w,
                           int N) {
    int idx = blockIdx.x * blockDim.x + threadIdx.x;
    if (idx >= N * KG * HH) return;
    int n = idx / (KG * HH);
    int c = idx % (KG * HH);
    float s = 0.f;
    for (int f = 0; f < FF; f++)
        s += x[(size_t)n * FF + f] * g1w[(size_t)f * (KG * HH) + c];
    g_gx1[idx] = s;
}

// ---------------- edge stage 1: WARP per edge (cleared pattern) --------------
// Lanes 0..7 compute the 8 gaussians with R3's exact expression; shfl
// broadcast; lane handles features 2*lane, 2*lane+1 via float2 gather.
__global__ __launch_bounds__(256) void edge1_kernel(const float* __restrict__ ea,
                                                    const float* __restrict__ mu1,
                                                    const float* __restrict__ sig1,
                                                    int E) {
    int w = (blockIdx.x * blockDim.x + threadIdx.x) >> 5;
    int lane = threadIdx.x & 31;
    if (w >= E) return;
    int r = g_rows[w], c = g_cols[w];
    float p0 = ea[2 * (size_t)w];
    float p1 = ea[2 * (size_t)w + 1];
    float g = 0.f;
    if (lane < KG) {
        float mx = mu1[lane * 2], my = mu1[lane * 2 + 1];
        float sx = sig1[lane * 2], sy = sig1[lane * 2 + 1];
        float dx = p0 - mx, dy = p1 - my;
        g = expf(-0.5f * (dx * dx / (1e-15f + sx * sx) +
                          dy * dy / (1e-15f + sy * sy)));
    }
    const float2* gx = (const float2*)(g_gx1 + (size_t)r * (KG * HH));
    float ax = 0.f, ay = 0.f;
#pragma unroll
    for (int k = 0; k < KG; k++) {
        float gk = __shfl_sync(0xffffffffu, g, k);
        float2 v = gx[k * 32 + lane];        // floats k*64 + 2*lane, +1
        ax += gk * v.x;
        ay += gk * v.y;
    }
    float* dst = g_agg1 + (size_t)c * HH + 2 * lane;
    atomicAdd(dst, ax);
    atomicAdd(dst + 1, ay);
}

// ---------------- node stage 1: mean + naive root matvec + bias + elu --------
// (PROVEN in R3 -- do not touch.)
__global__ void node1_kernel(const float* __restrict__ x,
                             const float* __restrict__ root1,
                             const float* __restrict__ bias1, int N) {
    int idx = blockIdx.x * blockDim.x + threadIdx.x;
    if (idx >= N * HH) return;
    int n = idx / HH, o = idx % HH;
    float cnt = fmaxf((float)g_cnt[n], 1.0f);
    float root = 0.f;
    for (int f = 0; f < FF; f++)
        root += x[(size_t)n * FF + f] * root1[(size_t)f * HH + o];
    float v = g_agg1[idx] / cnt + root + bias1[o];
    g_h[idx] = v > 0.f ? v : expm1f(v);
}

// ---------------- naive GEMM 2: gx2[n][c] = sum_f h[n][f] * g2_w[f][c] -------
// (PROVEN in R3 -- do not touch.)
__global__ void gx2_kernel(const float* __restrict__ g2w, int N) {
    int idx = blockIdx.x * blockDim.x + threadIdx.x;
    if (idx >= N * KG * CC) return;
    int n = idx / (KG * CC);
    int c = idx % (KG * CC);
    float s = 0.f;
    for (int f = 0; f < HH; f++)
        s += g_h[(size_t)n * HH + f] * g2w[(size_t)f * (KG * CC) + c];
    g_gx2[idx] = s;
}

// ---------------- edge stage 2: 4 edges per warp, 8 lanes each ---------------
// Lane sub computes gaussian sub for its group's edge (R3 expression), shfl
// within the 8-lane group; lane handles features 2*sub, 2*sub+1.
__global__ __launch_bounds__(256) void edge2_kernel(const float* __restrict__ ea,
                                                    const float* __restrict__ mu2,
                                                    const float* __restrict__ sig2,
                                                    int E) {
    int w = (blockIdx.x * blockDim.x + threadIdx.x) >> 5;
    int lane = threadIdx.x & 31;
    int sub = lane & 7, grp = lane >> 3;
    int e = w * 4 + grp;
    bool valid = (e < E);
    int r = 0, c = 0;
    float g = 0.f;
    if (valid) {
        r = g_rows[e];
        c = g_cols[e];
        float p0 = ea[2 * (size_t)e];
        float p1 = ea[2 * (size_t)e + 1];
        float mx = mu2[sub * 2], my = mu2[sub * 2 + 1];
        float sx = sig2[sub * 2], sy = sig2[sub * 2 + 1];
        float dx = p0 - mx, dy = p1 - my;
        g = expf(-0.5f * (dx * dx / (1e-15f + sx * sx) +
                          dy * dy / (1e-15f + sy * sy)));
    }
    const float2* gx = (const float2*)(g_gx2 + (size_t)r * (KG * CC));
    float ax = 0.f, ay = 0.f;
#pragma unroll
    for (int k = 0; k < KG; k++) {
        float gk = __shfl_sync(0xffffffffu, g, (grp << 3) + k);
        if (valid) {
            float2 v = gx[k * 8 + sub];      // floats k*16 + 2*sub, +1
            ax += gk * v.x;
            ay += gk * v.y;
        }
    }
    if (valid) {
        float* dst = g_agg2 + (size_t)c * CC + 2 * sub;
        atomicAdd(dst, ax);
        atomicAdd(dst + 1, ay);
    }
}

// ---------------- node stage 2: mean + naive root + bias + log_softmax -------
// (PROVEN in R3 -- do not touch.)
__global__ void node2_kernel(const float* __restrict__ root2,
                             const float* __restrict__ bias2,
                             float* __restrict__ out, int N) {
    int n = blockIdx.x * blockDim.x + threadIdx.x;
    if (n >= N) return;
    float cnt = fmaxf((float)g_cnt[n], 1.0f);
    float vals[CC];
    float m = -1e30f;
    for (int c = 0; c < CC; c++) {
        float root = 0.f;
        for (int f = 0; f < HH; f++)
            root += g_h[(size_t)n * HH + f] * root2[(size_t)f * CC + c];
        float v = g_agg2[(size_t)n * CC + c] / cnt + root + bias2[c];
        vals[c] = v;
        m = fmaxf(m, v);
    }
    float s = 0.f;
    for (int c = 0; c < CC; c++) s += expf(vals[c] - m);
    float lse = m + logf(s);
    for (int c = 0; c < CC; c++) out[(size_t)n * CC + c] = vals[c] - lse;
}

// ---------------- launch -----------------------------------------------------
extern "C" void kernel_launch(void* const* d_in, const int* in_sizes, int n_in,
                              void* d_out, int out_size) {
    const float* x      = (const float*)d_in[0];
    const void*  ei     = d_in[1];
    const float* ea     = (const float*)d_in[2];
    const float* g1_w   = (const float*)d_in[3];
    const float* mu1    = (const float*)d_in[4];
    const float* sig1   = (const float*)d_in[5];
    const float* root1  = (const float*)d_in[6];
    const float* bias1  = (const float*)d_in[7];
    const float* g2_w   = (const float*)d_in[8];
    const float* mu2    = (const float*)d_in[9];
    const float* sig2   = (const float*)d_in[10];
    const float* root2  = (const float*)d_in[11];
    const float* bias2  = (const float*)d_in[12];
    float* out = (float*)d_out;

    int N = in_sizes[0] / FF;       // 50000
    int E = in_sizes[2] / 2;        // 800000

    detect_kernel<<<1, 1>>>((const int*)ei);
    zero_kernel<<<(N * HH + 255) / 256, 256>>>(N);
    convert_edges<<<(E + 255) / 256, 256>>>(ei, E);

    // layer 1
    gx1_kernel<<<(N * KG * HH + 255) / 256, 256>>>(x, g1_w, N);
    edge1_kernel<<<(E + 7) / 8, 256>>>(ea, mu1, sig1, E);      // warp per edge
    node1_kernel<<<(N * HH + 255) / 256, 256>>>(x, root1, bias1, N);

    // layer 2
    gx2_kernel<<<(N * KG * CC + 255) / 256, 256>>>(g2_w, N);
    edge2_kernel<<<(E / 4 + 7) / 8, 256>>>(ea, mu2, sig2, E);  // 4 edges/warp
    node2_kernel<<<(N + 255) / 256, 256>>>(root2, bias2, out, N);
}

// round 9
// speedup vs baseline: 3.0164x; 1.3485x over previous
#include <cuda_runtime.h>
#include <math.h>

// Problem constants (fixed by setup_inputs)
#define NN   50000
#define EE   800000
#define FF   128
#define HH   64
#define CC   16
#define KG   8          // gaussian kernels

// ---------------- scratch (static device globals; no allocation) -------------
__device__ int   g_rows[EE];
__device__ int   g_cols[EE];
__device__ int   g_cnt[NN];
__device__ int   g_idx64;
__device__ float g_gx1[(size_t)NN * KG * HH];   // x @ g1_w   [N][512]
__device__ float g_agg1[NN * HH];
__device__ float g_h[NN * HH];
__device__ float g_gx2[(size_t)NN * KG * CC];   // h @ g2_w   [N][128]
__device__ float g_agg2[NN * CC];

// ---------------- dtype detect ------------------------------------------------
__global__ void detect_kernel(const int* __restrict__ ei_words) {
    // int64 little-endian with values < 2^31 -> every odd 32-bit word of the
    // first 128 entries is zero. int32 node ids in [0,50000) -> impossible.
    int allz = 1;
    for (int i = 0; i < 128; i++) {
        if (ei_words[2 * i + 1] != 0) { allz = 0; break; }
    }
    g_idx64 = allz;
}

// ---------------- zero accumulators ------------------------------------------
__global__ void zero_kernel(int N) {
    int i = blockIdx.x * blockDim.x + threadIdx.x;
    if (i < N * HH) g_agg1[i] = 0.f;
    if (i < N * CC) g_agg2[i] = 0.f;
    if (i < N)      g_cnt[i]  = 0;
}

// ---------------- edge index normalization + degree count --------------------
__global__ void convert_edges(const void* __restrict__ ei, int E) {
    int e = blockIdx.x * blockDim.x + threadIdx.x;
    if (e >= E) return;
    int r, c;
    if (g_idx64) {
        const long long* p = (const long long*)ei;
        r = (int)p[e];
        c = (int)p[(size_t)E + e];
    } else {
        const int* p = (const int*)ei;
        r = p[e];
        c = p[E + e];
    }
    g_rows[e] = r;
    g_cols[e] = c;
    atomicAdd(&g_cnt[c], 1);
}

// ---------------- gx1: one thread = one row, 4 cols (float4 B) ---------------
// gx1[n][c..c+3] = sum_f x[n][f] * g1w[f][c..c+3].  ONE A-row per thread
// (the empirically safe pattern); float4 only on the B/C side.
__global__ void gx1v_kernel(const float* __restrict__ x,
                            const float* __restrict__ g1w, int N) {
    int idx = blockIdx.x * blockDim.x + threadIdx.x;
    if (idx >= N * 128) return;          // 128 float4-quads per row of 512
    int n = idx >> 7;
    int c = (idx & 127) << 2;
    const float* xr = x + (size_t)n * FF;
    const float* bp = g1w + c;
    float ax = 0.f, ay = 0.f, az = 0.f, aw = 0.f;
    for (int f = 0; f < FF; f++) {
        float4 b = *(const float4*)(bp + (size_t)f * 512);
        float v = xr[f];
        ax += v * b.x; ay += v * b.y; az += v * b.z; aw += v * b.w;
    }
    *(float4*)(g_gx1 + (size_t)n * 512 + c) = make_float4(ax, ay, az, aw);
}

// ---------------- edge stage 1: WARP per edge (PROVEN in R7) -----------------
__global__ __launch_bounds__(256) void edge1_kernel(const float* __restrict__ ea,
                                                    const float* __restrict__ mu1,
                                                    const float* __restrict__ sig1,
                                                    int E) {
    int w = (blockIdx.x * blockDim.x + threadIdx.x) >> 5;
    int lane = threadIdx.x & 31;
    if (w >= E) return;
    int r = g_rows[w], c = g_cols[w];
    float p0 = ea[2 * (size_t)w];
    float p1 = ea[2 * (size_t)w + 1];
    float g = 0.f;
    if (lane < KG) {
        float mx = mu1[lane * 2], my = mu1[lane * 2 + 1];
        float sx = sig1[lane * 2], sy = sig1[lane * 2 + 1];
        float dx = p0 - mx, dy = p1 - my;
        g = expf(-0.5f * (dx * dx / (1e-15f + sx * sx) +
                          dy * dy / (1e-15f + sy * sy)));
    }
    const float2* gx = (const float2*)(g_gx1 + (size_t)r * (KG * HH));
    float ax = 0.f, ay = 0.f;
#pragma unroll
    for (int k = 0; k < KG; k++) {
        float gk = __shfl_sync(0xffffffffu, g, k);
        float2 v = gx[k * 32 + lane];        // floats k*64 + 2*lane, +1
        ax += gk * v.x;
        ay += gk * v.y;
    }
    float* dst = g_agg1 + (size_t)c * HH + 2 * lane;
    atomicAdd(dst, ax);
    atomicAdd(dst + 1, ay);
}

// ---------------- node stage 1: mean + naive root matvec + bias + elu --------
// (PROVEN in R3/R7 -- do not touch.)
__global__ void node1_kernel(const float* __restrict__ x,
                             const float* __restrict__ root1,
                             const float* __restrict__ bias1, int N) {
    int idx = blockIdx.x * blockDim.x + threadIdx.x;
    if (idx >= N * HH) return;
    int n = idx / HH, o = idx % HH;
    float cnt = fmaxf((float)g_cnt[n], 1.0f);
    float root = 0.f;
    for (int f = 0; f < FF; f++)
        root += x[(size_t)n * FF + f] * root1[(size_t)f * HH + o];
    float v = g_agg1[idx] / cnt + root + bias1[o];
    g_h[idx] = v > 0.f ? v : expm1f(v);
}

// ---------------- gx2: one thread = one row, 4 cols (float4 B) ---------------
__global__ void gx2v_kernel(const float* __restrict__ g2w, int N) {
    int idx = blockIdx.x * blockDim.x + threadIdx.x;
    if (idx >= N * 32) return;           // 32 float4-quads per row of 128
    int n = idx >> 5;
    int c = (idx & 31) << 2;
    const float* hr = g_h + (size_t)n * HH;
    const float* bp = g2w + c;
    float ax = 0.f, ay = 0.f, az = 0.f, aw = 0.f;
    for (int f = 0; f < HH; f++) {
        float4 b = *(const float4*)(bp + (size_t)f * 128);
        float v = hr[f];
        ax += v * b.x; ay += v * b.y; az += v * b.z; aw += v * b.w;
    }
    *(float4*)(g_gx2 + (size_t)n * 128 + c) = make_float4(ax, ay, az, aw);
}

// ---------------- edge stage 2: 4 edges per warp (PROVEN in R7) --------------
__global__ __launch_bounds__(256) void edge2_kernel(const float* __restrict__ ea,
                                                    const float* __restrict__ mu2,
                                                    const float* __restrict__ sig2,
                                                    int E) {
    int w = (blockIdx.x * blockDim.x + threadIdx.x) >> 5;
    int lane = threadIdx.x & 31;
    int sub = lane & 7, grp = lane >> 3;
    int e = w * 4 + grp;
    bool valid = (e < E);
    int r = 0, c = 0;
    float g = 0.f;
    if (valid) {
        r = g_rows[e];
        c = g_cols[e];
        float p0 = ea[2 * (size_t)e];
        float p1 = ea[2 * (size_t)e + 1];
        float mx = mu2[sub * 2], my = mu2[sub * 2 + 1];
        float sx = sig2[sub * 2], sy = sig2[sub * 2 + 1];
        float dx = p0 - mx, dy = p1 - my;
        g = expf(-0.5f * (dx * dx / (1e-15f + sx * sx) +
                          dy * dy / (1e-15f + sy * sy)));
    }
    const float2* gx = (const float2*)(g_gx2 + (size_t)r * (KG * CC));
    float ax = 0.f, ay = 0.f;
#pragma unroll
    for (int k = 0; k < KG; k++) {
        float gk = __shfl_sync(0xffffffffu, g, (grp << 3) + k);
        if (valid) {
            float2 v = gx[k * 8 + sub];      // floats k*16 + 2*sub, +1
            ax += gk * v.x;
            ay += gk * v.y;
        }
    }
    if (valid) {
        float* dst = g_agg2 + (size_t)c * CC + 2 * sub;
        atomicAdd(dst, ax);
        atomicAdd(dst + 1, ay);
    }
}

// ---------------- node stage 2: mean + naive root + bias + log_softmax -------
// (PROVEN in R3/R7 -- do not touch.)
__global__ void node2_kernel(const float* __restrict__ root2,
                             const float* __restrict__ bias2,
                             float* __restrict__ out, int N) {
    int n = blockIdx.x * blockDim.x + threadIdx.x;
    if (n >= N) return;
    float cnt = fmaxf((float)g_cnt[n], 1.0f);
    float vals[CC];
    float m = -1e30f;
    for (int c = 0; c < CC; c++) {
        float root = 0.f;
        for (int f = 0; f < HH; f++)
            root += g_h[(size_t)n * HH + f] * root2[(size_t)f * CC + c];
        float v = g_agg2[(size_t)n * CC + c] / cnt + root + bias2[c];
        vals[c] = v;
        m = fmaxf(m, v);
    }
    float s = 0.f;
    for (int c = 0; c < CC; c++) s += expf(vals[c] - m);
    float lse = m + logf(s);
    for (int c = 0; c < CC; c++) out[(size_t)n * CC + c] = vals[c] - lse;
}

// ---------------- launch -----------------------------------------------------
extern "C" void kernel_launch(void* const* d_in, const int* in_sizes, int n_in,
                              void* d_out, int out_size) {
    const float* x      = (const float*)d_in[0];
    const void*  ei     = d_in[1];
    const float* ea     = (const float*)d_in[2];
    const float* g1_w   = (const float*)d_in[3];
    const float* mu1    = (const float*)d_in[4];
    const float* sig1   = (const float*)d_in[5];
    const float* root1  = (const float*)d_in[6];
    const float* bias1  = (const float*)d_in[7];
    const float* g2_w   = (const float*)d_in[8];
    const float* mu2    = (const float*)d_in[9];
    const float* sig2   = (const float*)d_in[10];
    const float* root2  = (const float*)d_in[11];
    const float* bias2  = (const float*)d_in[12];
    float* out = (float*)d_out;

    int N = in_sizes[0] / FF;       // 50000
    int E = in_sizes[2] / 2;        // 800000

    detect_kernel<<<1, 1>>>((const int*)ei);
    zero_kernel<<<(N * HH + 255) / 256, 256>>>(N);
    convert_edges<<<(E + 255) / 256, 256>>>(ei, E);

    // layer 1
    gx1v_kernel<<<(N * 128 + 255) / 256, 256>>>(x, g1_w, N);
    edge1_kernel<<<(E + 7) / 8, 256>>>(ea, mu1, sig1, E);      // warp per edge
    node1_kernel<<<(N * HH + 255) / 256, 256>>>(x, root1, bias1, N);

    // layer 2
    gx2v_kernel<<<(N * 32 + 255) / 256, 256>>>(g2_w, N);
    edge2_kernel<<<(E / 4 + 7) / 8, 256>>>(ea, mu2, sig2, E);  // 4 edges/warp
    node2_kernel<<<(N + 255) / 256, 256>>>(root2, bias2, out, N);
}

// round 10
// speedup vs baseline: 4.5001x; 1.4919x over previous
#include <cuda_runtime.h>
#include <math.h>

// Problem constants (fixed by setup_inputs)
#define NN   50000
#define EE   800000
#define FF   128
#define HH   64
#define CC   16
#define KG   8          // gaussian kernels

// ---------------- scratch (static device globals; no allocation) -------------
// RULE (hard-won): NEVER pass these symbols as kernel arguments from host
// code. On GB300 (ATS) the host-shadow address is silently writable and the
// kernel reads/writes host memory -> device readers see zeros. Reference
// them INSIDE kernel bodies only.
__device__ int   g_rows[EE];
__device__ int   g_cols[EE];
__device__ int   g_cnt[NN];
__device__ int   g_idx64;
__device__ float g_gx1[(size_t)NN * KG * HH];   // x @ g1_w    [N][512]
__device__ float g_r1 [(size_t)NN * HH];        // x @ root1_w [N][64]
__device__ float g_agg1[NN * HH];
__device__ float g_h[NN * HH];
__device__ float g_gx2[(size_t)NN * KG * CC];   // h @ g2_w    [N][128]
__device__ float g_agg2[NN * CC];

// ---------------- dtype detect ------------------------------------------------
__global__ void detect_kernel(const int* __restrict__ ei_words) {
    int allz = 1;
    for (int i = 0; i < 128; i++) {
        if (ei_words[2 * i + 1] != 0) { allz = 0; break; }
    }
    g_idx64 = allz;
}

// ---------------- zero accumulators ------------------------------------------
__global__ void zero_kernel(int N) {
    int i = blockIdx.x * blockDim.x + threadIdx.x;
    if (i < N * HH) g_agg1[i] = 0.f;
    if (i < N * CC) g_agg2[i] = 0.f;
    if (i < N)      g_cnt[i]  = 0;
}

// ---------------- edge index normalization + degree count --------------------
__global__ void convert_edges(const void* __restrict__ ei, int E) {
    int e = blockIdx.x * blockDim.x + threadIdx.x;
    if (e >= E) return;
    int r, c;
    if (g_idx64) {
        const long long* p = (const long long*)ei;
        r = (int)p[e];
        c = (int)p[(size_t)E + e];
    } else {
        const int* p = (const int*)ei;
        r = p[e];
        c = p[E + e];
    }
    g_rows[e] = r;
    g_cols[e] = c;
    atomicAdd(&g_cnt[c], 1);
}

// ---------------- smem-tiled GEMM: C = A @ B, row-major ----------------------
// BM=BN=64, BK=16, 256 threads, 4x4 microtile. N%64==0, K%16==0, M guarded.
// MODE selects device-global operands IN-KERNEL (never via host args):
//   MODE 0: A=Aarg(x),  C=g_gx1   (N=512, K=128)
//   MODE 1: A=Aarg(x),  C=g_r1    (N=64,  K=128)
//   MODE 2: A=g_h,      C=g_gx2   (N=128, K=64)
template <int MODE>
__global__ __launch_bounds__(256) void gemm_tile(const float* __restrict__ Aarg,
                                                 const float* __restrict__ B,
                                                 int M, int N, int K) {
    const float* A = (MODE == 2) ? (const float*)g_h : Aarg;
    float* C = (MODE == 0) ? g_gx1 : (MODE == 1) ? g_r1 : g_gx2;

    const int bm = blockIdx.y * 64;
    const int bn = blockIdx.x * 64;
    __shared__ float sA[16][64];   // sA[k][m]
    __shared__ float sB[16][64];   // sB[k][n]
    const int t = threadIdx.x;
    const int mt = (t >> 4) << 2;        // row sub-tile 0..60
    const int nt = (t & 15) << 2;        // col sub-tile 0..60
    const int la_m = t >> 2;             // 0..63
    const int la_k = (t & 3) << 2;       // 0,4,8,12
    const int lb_k = t >> 4;             // 0..15
    const int lb_n = (t & 15) << 2;      // 0..60

    const bool arow_ok = (bm + la_m) < M;
    const float* Aptr = A + (size_t)(bm + la_m) * K + la_k;
    float acc[4][4] = {};

    for (int k0 = 0; k0 < K; k0 += 16) {
        float4 a4 = make_float4(0.f, 0.f, 0.f, 0.f);
        if (arow_ok) a4 = *(const float4*)(Aptr + k0);
        sA[la_k + 0][la_m] = a4.x;
        sA[la_k + 1][la_m] = a4.y;
        sA[la_k + 2][la_m] = a4.z;
        sA[la_k + 3][la_m] = a4.w;
        *(float4*)&sB[lb_k][lb_n] =
            *(const float4*)(B + (size_t)(k0 + lb_k) * N + bn + lb_n);
        __syncthreads();
#pragma unroll
        for (int kk = 0; kk < 16; kk++) {
            float4 a = *(const float4*)&sA[kk][mt];
            float4 b = *(const float4*)&sB[kk][nt];
            acc[0][0] += a.x * b.x; acc[0][1] += a.x * b.y;
            acc[0][2] += a.x * b.z; acc[0][3] += a.x * b.w;
            acc[1][0] += a.y * b.x; acc[1][1] += a.y * b.y;
            acc[1][2] += a.y * b.z; acc[1][3] += a.y * b.w;
            acc[2][0] += a.z * b.x; acc[2][1] += a.z * b.y;
            acc[2][2] += a.z * b.z; acc[2][3] += a.z * b.w;
            acc[3][0] += a.w * b.x; acc[3][1] += a.w * b.y;
            acc[3][2] += a.w * b.z; acc[3][3] += a.w * b.w;
        }
        __syncthreads();
    }
#pragma unroll
    for (int i = 0; i < 4; i++) {
        int r = bm + mt + i;
        if (r < M) {
            float4 o = make_float4(acc[i][0], acc[i][1], acc[i][2], acc[i][3]);
            *(float4*)(C + (size_t)r * N + bn + nt) = o;
        }
    }
}

// ---------------- edge stage 1: WARP per edge (PROVEN R7/R9) -----------------
__global__ __launch_bounds__(256) void edge1_kernel(const float* __restrict__ ea,
                                                    const float* __restrict__ mu1,
                                                    const float* __restrict__ sig1,
                                                    int E) {
    int w = (blockIdx.x * blockDim.x + threadIdx.x) >> 5;
    int lane = threadIdx.x & 31;
    if (w >= E) return;
    int r = g_rows[w], c = g_cols[w];
    float p0 = ea[2 * (size_t)w];
    float p1 = ea[2 * (size_t)w + 1];
    float g = 0.f;
    if (lane < KG) {
        float mx = mu1[lane * 2], my = mu1[lane * 2 + 1];
        float sx = sig1[lane * 2], sy = sig1[lane * 2 + 1];
        float dx = p0 - mx, dy = p1 - my;
        g = expf(-0.5f * (dx * dx / (1e-15f + sx * sx) +
                          dy * dy / (1e-15f + sy * sy)));
    }
    const float2* gx = (const float2*)(g_gx1 + (size_t)r * (KG * HH));
    float ax = 0.f, ay = 0.f;
#pragma unroll
    for (int k = 0; k < KG; k++) {
        float gk = __shfl_sync(0xffffffffu, g, k);
        float2 v = gx[k * 32 + lane];
        ax += gk * v.x;
        ay += gk * v.y;
    }
    float* dst = g_agg1 + (size_t)c * HH + 2 * lane;
    atomicAdd(dst, ax);
    atomicAdd(dst + 1, ay);
}

// ---------------- node stage 1: mean + precomputed root + bias + elu ---------
__global__ void node1_kernel(const float* __restrict__ bias1, int N) {
    int i = blockIdx.x * blockDim.x + threadIdx.x;
    if (i >= N * HH) return;
    int n = i >> 6, o = i & 63;
    float cnt = fmaxf((float)g_cnt[n], 1.0f);
    float v = g_agg1[i] / cnt + g_r1[i] + bias1[o];
    g_h[i] = v > 0.f ? v : expm1f(v);
}

// ---------------- edge stage 2: 4 edges per warp (PROVEN R7/R9) --------------
__global__ __launch_bounds__(256) void edge2_kernel(const float* __restrict__ ea,
                                                    const float* __restrict__ mu2,
                                                    const float* __restrict__ sig2,
                                                    int E) {
    int w = (blockIdx.x * blockDim.x + threadIdx.x) >> 5;
    int lane = threadIdx.x & 31;
    int sub = lane & 7, grp = lane >> 3;
    int e = w * 4 + grp;
    bool valid = (e < E);
    int r = 0, c = 0;
    float g = 0.f;
    if (valid) {
        r = g_rows[e];
        c = g_cols[e];
        float p0 = ea[2 * (size_t)e];
        float p1 = ea[2 * (size_t)e + 1];
        float mx = mu2[sub * 2], my = mu2[sub * 2 + 1];
        float sx = sig2[sub * 2], sy = sig2[sub * 2 + 1];
        float dx = p0 - mx, dy = p1 - my;
        g = expf(-0.5f * (dx * dx / (1e-15f + sx * sx) +
                          dy * dy / (1e-15f + sy * sy)));
    }
    const float2* gx = (const float2*)(g_gx2 + (size_t)r * (KG * CC));
    float ax = 0.f, ay = 0.f;
#pragma unroll
    for (int k = 0; k < KG; k++) {
        float gk = __shfl_sync(0xffffffffu, g, (grp << 3) + k);
        if (valid) {
            float2 v = gx[k * 8 + sub];
            ax += gk * v.x;
            ay += gk * v.y;
        }
    }
    if (valid) {
        float* dst = g_agg2 + (size_t)c * CC + 2 * sub;
        atomicAdd(dst, ax);
        atomicAdd(dst + 1, ay);
    }
}

// ---------------- node stage 2: mean + inline root + bias + log_softmax ------
// (PROVEN R3/R7/R9 -- do not touch.)
__global__ void node2_kernel(const float* __restrict__ root2,
                             const float* __restrict__ bias2,
                             float* __restrict__ out, int N) {
    int n = blockIdx.x * blockDim.x + threadIdx.x;
    if (n >= N) return;
    float cnt = fmaxf((float)g_cnt[n], 1.0f);
    float vals[CC];
    float m = -1e30f;
    for (int c = 0; c < CC; c++) {
        float root = 0.f;
        for (int f = 0; f < HH; f++)
            root += g_h[(size_t)n * HH + f] * root2[(size_t)f * CC + c];
        float v = g_agg2[(size_t)n * CC + c] / cnt + root + bias2[c];
        vals[c] = v;
        m = fmaxf(m, v);
    }
    float s = 0.f;
    for (int c = 0; c < CC; c++) s += expf(vals[c] - m);
    float lse = m + logf(s);
    for (int c = 0; c < CC; c++) out[(size_t)n * CC + c] = vals[c] - lse;
}

// ---------------- launch -----------------------------------------------------
extern "C" void kernel_launch(void* const* d_in, const int* in_sizes, int n_in,
                              void* d_out, int out_size) {
    const float* x      = (const float*)d_in[0];
    const void*  ei     = d_in[1];
    const float* ea     = (const float*)d_in[2];
    const float* g1_w   = (const float*)d_in[3];
    const float* mu1    = (const float*)d_in[4];
    const float* sig1   = (const float*)d_in[5];
    const float* root1  = (const float*)d_in[6];
    const float* bias1  = (const float*)d_in[7];
    const float* g2_w   = (const float*)d_in[8];
    const float* mu2    = (const float*)d_in[9];
    const float* sig2   = (const float*)d_in[10];
    const float* root2  = (const float*)d_in[11];
    const float* bias2  = (const float*)d_in[12];
    float* out = (float*)d_out;

    int N = in_sizes[0] / FF;       // 50000
    int E = in_sizes[2] / 2;        // 800000

    detect_kernel<<<1, 1>>>((const int*)ei);
    zero_kernel<<<(N * HH + 255) / 256, 256>>>(N);
    convert_edges<<<(E + 255) / 256, 256>>>(ei, E);

    int mb = (N + 63) / 64;         // 782

    // layer 1
    gemm_tile<0><<<dim3(512 / 64, mb), 256>>>(x, g1_w, N, 512, FF);   // gx1
    gemm_tile<1><<<dim3(64 / 64, mb), 256>>>(x, root1, N, 64, FF);    // r1
    edge1_kernel<<<(E + 7) / 8, 256>>>(ea, mu1, sig1, E);
    node1_kernel<<<(N * HH + 255) / 256, 256>>>(bias1, N);

    // layer 2
    gemm_tile<2><<<dim3(128 / 64, mb), 256>>>(nullptr, g2_w, N, 128, HH); // gx2
    edge2_kernel<<<(E / 4 + 7) / 8, 256>>>(ea, mu2, sig2, E);
    node2_kernel<<<(N + 255) / 256, 256>>>(root2, bias2, out, N);
}

// round 11
// speedup vs baseline: 4.7636x; 1.0586x over previous
#include <cuda_runtime.h>
#include <math.h>

// Problem constants (fixed by setup_inputs)
#define NN   50000
#define EE   800000
#define FF   128
#define HH   64
#define CC   16
#define KG   8          // gaussian kernels

// ---------------- scratch (static device globals; no allocation) -------------
// RULE (hard-won): NEVER pass these symbols as kernel arguments from host
// code. On GB300 (ATS) the host-shadow address is silently writable and the
// kernel reads/writes host memory -> device readers see zeros. Reference
// them INSIDE kernel bodies only.
__device__ int   g_rows[EE];
__device__ int   g_cols[EE];
__device__ int   g_cnt[NN];
__device__ int   g_idx64;
__device__ float g_gx1[(size_t)NN * KG * HH];   // x @ g1_w    [N][512]
__device__ float g_r1 [(size_t)NN * HH];        // x @ root1_w [N][64]
__device__ float g_agg1[NN * HH];
__device__ float g_h[NN * HH];
__device__ float g_gx2[(size_t)NN * KG * CC];   // h @ g2_w    [N][128]
__device__ float g_agg2[NN * CC];

// ---------------- dtype detect ------------------------------------------------
__global__ void detect_kernel(const int* __restrict__ ei_words) {
    int allz = 1;
    for (int i = 0; i < 128; i++) {
        if (ei_words[2 * i + 1] != 0) { allz = 0; break; }
    }
    g_idx64 = allz;
}

// ---------------- zero accumulators ------------------------------------------
__global__ void zero_kernel(int N) {
    int i = blockIdx.x * blockDim.x + threadIdx.x;
    if (i < N * HH) g_agg1[i] = 0.f;
    if (i < N * CC) g_agg2[i] = 0.f;
    if (i < N)      g_cnt[i]  = 0;
}

// ---------------- edge index normalization + degree count --------------------
__global__ void convert_edges(const void* __restrict__ ei, int E) {
    int e = blockIdx.x * blockDim.x + threadIdx.x;
    if (e >= E) return;
    int r, c;
    if (g_idx64) {
        const long long* p = (const long long*)ei;
        r = (int)p[e];
        c = (int)p[(size_t)E + e];
    } else {
        const int* p = (const int*)ei;
        r = p[e];
        c = p[E + e];
    }
    g_rows[e] = r;
    g_cols[e] = c;
    atomicAdd(&g_cnt[c], 1);
}

// ---------------- smem-tiled GEMM: C = A @ B, row-major ----------------------
// BM=128, BN=64, BK=16, 256 threads, 8x4 microtile. N%64==0, K%16==0,
// M guarded. grid = (N/64, ceil(M/128)).
// MODE selects device-global operands IN-KERNEL (never via host args):
//   MODE 0: A=Aarg(x),  C=g_gx1   (N=512, K=128)
//   MODE 1: A=Aarg(x),  C=g_r1    (N=64,  K=128)
//   MODE 2: A=g_h,      C=g_gx2   (N=128, K=64)
template <int MODE>
__global__ __launch_bounds__(256) void gemm_tile(const float* __restrict__ Aarg,
                                                 const float* __restrict__ B,
                                                 int M, int N, int K) {
    const float* A = (MODE == 2) ? (const float*)g_h : Aarg;
    float* C = (MODE == 0) ? g_gx1 : (MODE == 1) ? g_r1 : g_gx2;

    const int bm = blockIdx.y * 128;
    const int bn = blockIdx.x * 64;
    __shared__ float sA[16][128];  // sA[k][m]
    __shared__ float sB[16][64];   // sB[k][n]
    const int t = threadIdx.x;
    const int mt = (t >> 4) << 3;        // row sub-tile 0..120 (8 rows)
    const int nt = (t & 15) << 2;        // col sub-tile 0..60 (4 cols)
    // A-load: thread t loads A[bm + t/2][k0 + (t%2)*8 .. +7] (2 float4)
    const int la_m = t >> 1;             // 0..127
    const int la_k = (t & 1) << 3;       // 0 or 8
    // B-load: thread t loads B[k0 + t/16][bn + (t%16)*4 .. +3]
    const int lb_k = t >> 4;             // 0..15
    const int lb_n = (t & 15) << 2;      // 0..60

    const bool arow_ok = (bm + la_m) < M;
    const float* Aptr = A + (size_t)(bm + la_m) * K + la_k;
    float acc[8][4] = {};

    for (int k0 = 0; k0 < K; k0 += 16) {
        float4 a4 = make_float4(0.f, 0.f, 0.f, 0.f);
        float4 a4b = make_float4(0.f, 0.f, 0.f, 0.f);
        if (arow_ok) {
            a4  = *(const float4*)(Aptr + k0);
            a4b = *(const float4*)(Aptr + k0 + 4);
        }
        sA[la_k + 0][la_m] = a4.x;
        sA[la_k + 1][la_m] = a4.y;
        sA[la_k + 2][la_m] = a4.z;
        sA[la_k + 3][la_m] = a4.w;
        sA[la_k + 4][la_m] = a4b.x;
        sA[la_k + 5][la_m] = a4b.y;
        sA[la_k + 6][la_m] = a4b.z;
        sA[la_k + 7][la_m] = a4b.w;
        *(float4*)&sB[lb_k][lb_n] =
            *(const float4*)(B + (size_t)(k0 + lb_k) * N + bn + lb_n);
        __syncthreads();
#pragma unroll
        for (int kk = 0; kk < 16; kk++) {
            float4 a_lo = *(const float4*)&sA[kk][mt];
            float4 a_hi = *(const float4*)&sA[kk][mt + 4];
            float4 b = *(const float4*)&sB[kk][nt];
            float ra[8] = {a_lo.x, a_lo.y, a_lo.z, a_lo.w,
                           a_hi.x, a_hi.y, a_hi.z, a_hi.w};
#pragma unroll
            for (int i = 0; i < 8; i++) {
                acc[i][0] += ra[i] * b.x;
                acc[i][1] += ra[i] * b.y;
                acc[i][2] += ra[i] * b.z;
                acc[i][3] += ra[i] * b.w;
            }
        }
        __syncthreads();
    }
#pragma unroll
    for (int i = 0; i < 8; i++) {
        int r = bm + mt + i;
        if (r < M) {
            float4 o = make_float4(acc[i][0], acc[i][1], acc[i][2], acc[i][3]);
            *(float4*)(C + (size_t)r * N + bn + nt) = o;
        }
    }
}

// ---------------- edge stage 1: WARP per edge + vector red -------------------
__global__ __launch_bounds__(256) void edge1_kernel(const float* __restrict__ ea,
                                                    const float* __restrict__ mu1,
                                                    const float* __restrict__ sig1,
                                                    int E) {
    int w = (blockIdx.x * blockDim.x + threadIdx.x) >> 5;
    int lane = threadIdx.x & 31;
    if (w >= E) return;
    int r = g_rows[w], c = g_cols[w];
    float p0 = ea[2 * (size_t)w];
    float p1 = ea[2 * (size_t)w + 1];
    float g = 0.f;
    if (lane < KG) {
        float mx = mu1[lane * 2], my = mu1[lane * 2 + 1];
        float sx = sig1[lane * 2], sy = sig1[lane * 2 + 1];
        float dx = p0 - mx, dy = p1 - my;
        g = expf(-0.5f * (dx * dx / (1e-15f + sx * sx) +
                          dy * dy / (1e-15f + sy * sy)));
    }
    const float2* gx = (const float2*)(g_gx1 + (size_t)r * (KG * HH));
    float ax = 0.f, ay = 0.f;
#pragma unroll
    for (int k = 0; k < KG; k++) {
        float gk = __shfl_sync(0xffffffffu, g, k);
        float2 v = gx[k * 32 + lane];
        ax += gk * v.x;
        ay += gk * v.y;
    }
    float* dst = g_agg1 + (size_t)c * HH + 2 * lane;
    asm volatile("red.global.add.v2.f32 [%0], {%1, %2};" ::"l"(dst), "f"(ax),
                 "f"(ay) : "memory");
}

// ---------------- node stage 1: mean + precomputed root + bias + elu ---------
__global__ void node1_kernel(const float* __restrict__ bias1, int N) {
    int i = blockIdx.x * blockDim.x + threadIdx.x;
    if (i >= N * HH) return;
    int n = i >> 6, o = i & 63;
    float cnt = fmaxf((float)g_cnt[n], 1.0f);
    float v = g_agg1[i] / cnt + g_r1[i] + bias1[o];
    g_h[i] = v > 0.f ? v : expm1f(v);
}

// ---------------- edge stage 2: 4 edges per warp + vector red ----------------
__global__ __launch_bounds__(256) void edge2_kernel(const float* __restrict__ ea,
                                                    const float* __restrict__ mu2,
                                                    const float* __restrict__ sig2,
                                                    int E) {
    int w = (blockIdx.x * blockDim.x + threadIdx.x) >> 5;
    int lane = threadIdx.x & 31;
    int sub = lane & 7, grp = lane >> 3;
    int e = w * 4 + grp;
    bool valid = (e < E);
    int r = 0, c = 0;
    float g = 0.f;
    if (valid) {
        r = g_rows[e];
        c = g_cols[e];
        float p0 = ea[2 * (size_t)e];
        float p1 = ea[2 * (size_t)e + 1];
        float mx = mu2[sub * 2], my = mu2[sub * 2 + 1];
        float sx = sig2[sub * 2], sy = sig2[sub * 2 + 1];
        float dx = p0 - mx, dy = p1 - my;
        g = expf(-0.5f * (dx * dx / (1e-15f + sx * sx) +
                          dy * dy / (1e-15f + sy * sy)));
    }
    const float2* gx = (const float2*)(g_gx2 + (size_t)r * (KG * CC));
    float ax = 0.f, ay = 0.f;
#pragma unroll
    for (int k = 0; k < KG; k++) {
        float gk = __shfl_sync(0xffffffffu, g, (grp << 3) + k);
        if (valid) {
            float2 v = gx[k * 8 + sub];
            ax += gk * v.x;
            ay += gk * v.y;
        }
    }
    if (valid) {
        float* dst = g_agg2 + (size_t)c * CC + 2 * sub;
        asm volatile("red.global.add.v2.f32 [%0], {%1, %2};" ::"l"(dst),
                     "f"(ax), "f"(ay) : "memory");
    }
}

// ---------------- node stage 2: mean + inline root + bias + log_softmax ------
// (PROVEN R3/R7/R9/R10 -- do not touch.)
__global__ void node2_kernel(const float* __restrict__ root2,
                             const float* __restrict__ bias2,
                             float* __restrict__ out, int N) {
    int n = blockIdx.x * blockDim.x + threadIdx.x;
    if (n >= N) return;
    float cnt = fmaxf((float)g_cnt[n], 1.0f);
    float vals[CC];
    float m = -1e30f;
    for (int c = 0; c < CC; c++) {
        float root = 0.f;
        for (int f = 0; f < HH; f++)
            root += g_h[(size_t)n * HH + f] * root2[(size_t)f * CC + c];
        float v = g_agg2[(size_t)n * CC + c] / cnt + root + bias2[c];
        vals[c] = v;
        m = fmaxf(m, v);
    }
    float s = 0.f;
    for (int c = 0; c < CC; c++) s += expf(vals[c] - m);
    float lse = m + logf(s);
    for (int c = 0; c < CC; c++) out[(size_t)n * CC + c] = vals[c] - lse;
}

// ---------------- launch -----------------------------------------------------
extern "C" void kernel_launch(void* const* d_in, const int* in_sizes, int n_in,
                              void* d_out, int out_size) {
    const float* x      = (const float*)d_in[0];
    const void*  ei     = d_in[1];
    const float* ea     = (const float*)d_in[2];
    const float* g1_w   = (const float*)d_in[3];
    const float* mu1    = (const float*)d_in[4];
    const float* sig1   = (const float*)d_in[5];
    const float* root1  = (const float*)d_in[6];
    const float* bias1  = (const float*)d_in[7];
    const float* g2_w   = (const float*)d_in[8];
    const float* mu2    = (const float*)d_in[9];
    const float* sig2   = (const float*)d_in[10];
    const float* root2  = (const float*)d_in[11];
    const float* bias2  = (const float*)d_in[12];
    float* out = (float*)d_out;

    int N = in_sizes[0] / FF;       // 50000
    int E = in_sizes[2] / 2;        // 800000

    detect_kernel<<<1, 1>>>((const int*)ei);
    zero_kernel<<<(N * HH + 255) / 256, 256>>>(N);
    convert_edges<<<(E + 255) / 256, 256>>>(ei, E);

    int mb = (N + 127) / 128;       // 391

    // layer 1
    gemm_tile<0><<<dim3(512 / 64, mb), 256>>>(x, g1_w, N, 512, FF);   // gx1
    gemm_tile<1><<<dim3(64 / 64, mb), 256>>>(x, root1, N, 64, FF);    // r1
    edge1_kernel<<<(E + 7) / 8, 256>>>(ea, mu1, sig1, E);
    node1_kernel<<<(N * HH + 255) / 256, 256>>>(bias1, N);

    // layer 2
    gemm_tile<2><<<dim3(128 / 64, mb), 256>>>(nullptr, g2_w, N, 128, HH); // gx2
    edge2_kernel<<<(E / 4 + 7) / 8, 256>>>(ea, mu2, sig2, E);
    node2_kernel<<<(N + 255) / 256, 256>>>(root2, bias2, out, N);
}